// round 12
// baseline (speedup 1.0000x reference)
#include <cuda_runtime.h>
#include <cstdint>
#include <cstddef>

// ---------------------------------------------------------------------------
// Problem constants
// ---------------------------------------------------------------------------
#define Sq      1024
#define Hd      4096
#define NHEAD   32
#define HDIM    128
#define RLORA   16
#define NELEM   (Sq * Hd)                   // 4194304
#define WELEM   (Hd * Hd)                   // 16777216
#define AELEM   ((size_t)NHEAD * Sq * Sq)   // 33554432
#define BIGN    2097152u                    // 2^21 bins per tensor

// Arch-specific (sm_103a) feature gate.
#if defined(__CUDA_ARCH_FEAT_SM103_ALL) || defined(__CUDA_ARCH_FEAT_SM100_ALL) || \
    defined(__CUDA_ARCH_FEAT_SM101_ALL)
#define TC_OK 1
#else
#define TC_OK 0
#endif

// ---------------------------------------------------------------------------
// Device scratch (static: no allocation allowed)
// ---------------------------------------------------------------------------
__device__ float g_Aaug[NELEM];               // rounded A (x, later attn out)
__device__ float g_Baug[WELEM];               // dequant W + folded lora
__device__ float g_q[NELEM];
__device__ float g_k[NELEM];
__device__ float g_v[NELEM];
__device__ float g_vt[NELEM];                 // V transposed: [4096 d][1024 k]
__device__ float g_attn[AELEM];               // scores -> probs (tf32-rounded)

// selection state (per-tensor, 6 tensors)
__device__ unsigned g_h1[6][2048], g_h2[6][2048];
__device__ unsigned g_big[6][BIGN];           // full low-21-bit histogram (48MB)

struct SelArgs {
    const float*       d[6];
    unsigned long long n[6];
    unsigned long long k[6];
};

__constant__ float c_nf4[16] = {
    -1.0f, -0.6961928009986877f, -0.5250730514526367f, -0.39491748809814453f,
    -0.28444138169288635f, -0.18477343022823334f, -0.09105003625154495f, 0.0f,
    0.07958029955625534f, 0.16093020141124725f, 0.24611230194568634f,
    0.33791524171829224f, 0.4407098591327667f, 0.5626170039176941f,
    0.7229568362236023f, 1.0f };

// ---------------------------------------------------------------------------
// PTX helpers
// ---------------------------------------------------------------------------
__device__ __forceinline__ uint32_t smem_u32(const void* p) {
    uint32_t a;
    asm("{ .reg .u64 t; cvta.to.shared.u64 t, %1; cvt.u32.u64 %0, t; }"
        : "=r"(a) : "l"(p));
    return a;
}
__device__ __forceinline__ bool elect_one() {
    uint32_t pred;
    asm volatile("{\n\t.reg .pred p;\n\telect.sync _|p, 0xFFFFFFFF;\n\t"
                 "selp.b32 %0, 1, 0, p;\n\t}" : "=r"(pred));
    return pred != 0;
}
__device__ __forceinline__ float tf32r(float v) {
    unsigned u;
    asm("cvt.rna.tf32.f32 %0, %1;" : "=r"(u) : "f"(v));
    return __uint_as_float(u);
}
__device__ __forceinline__ unsigned swz(unsigned off) {   // SW128 swizzle
    return off ^ ((off >> 3) & 0x70);
}
__device__ __forceinline__ void cpa16(unsigned dst, const void* src) {
    asm volatile("cp.async.cg.shared.global [%0], [%1], 16;"
                 :: "r"(dst), "l"(src));
}

static constexpr uint64_t SMEM_DESC_BASE_SW128 =
    (uint64_t(2)  << 61) | (uint64_t(1) << 46) |
    (uint64_t(64) << 32) | (uint64_t(1) << 16);
#define MAKE_SMEM_DESC(base_addr) \
    (SMEM_DESC_BASE_SW128 | ((uint64_t)((base_addr) >> 4) & 0x3FFF))

#define MBARRIER_INIT(mbar, count) \
    asm volatile("mbarrier.init.shared.b64 [%0], %1;" \
        :: "r"((uint32_t)(mbar)), "r"((uint32_t)(count)) : "memory")

#define MBARRIER_WAIT_PARITY(mbar_smem_addr, phase_parity) do { \
    uint32_t _mbar = (uint32_t)(mbar_smem_addr); \
    uint32_t _parity = (uint32_t)(phase_parity); \
    uint32_t _done; \
    asm volatile("{\n\t.reg .pred p;\n\t" \
        "mbarrier.try_wait.parity.acquire.cta.shared::cta.b64 p, [%1], %2;\n\t" \
        "selp.b32 %0, 1, 0, p;\n\t}" \
        : "=r"(_done) : "r"(_mbar), "r"(_parity) : "memory"); \
    if (!_done) { \
        asm volatile("{\n\t.reg .pred P1;\n\t" \
            "WAIT_LOOP_%=:\n\t" \
            "mbarrier.try_wait.parity.acquire.cta.shared::cta.b64 P1, [%0], %1, 0x989680;\n\t" \
            "@P1 bra.uni WAIT_DONE_%=;\n\t" \
            "bra.uni WAIT_LOOP_%=;\n\t" \
            "WAIT_DONE_%=:\n\t}" \
            :: "r"(_mbar), "r"(_parity) : "memory"); \
    } \
} while (0)

// cluster-scope acquire variant (waiter side of a cross-CTA release-arrive)
#define MBARRIER_WAIT_PARITY_CL(mbar_smem_addr, phase_parity) do { \
    uint32_t _mbar = (uint32_t)(mbar_smem_addr); \
    uint32_t _parity = (uint32_t)(phase_parity); \
    uint32_t _done; \
    asm volatile("{\n\t.reg .pred p;\n\t" \
        "mbarrier.try_wait.parity.acquire.cluster.shared::cta.b64 p, [%1], %2;\n\t" \
        "selp.b32 %0, 1, 0, p;\n\t}" \
        : "=r"(_done) : "r"(_mbar), "r"(_parity) : "memory"); \
    if (!_done) { \
        asm volatile("{\n\t.reg .pred P1;\n\t" \
            "WAIT_LOOPC_%=:\n\t" \
            "mbarrier.try_wait.parity.acquire.cluster.shared::cta.b64 P1, [%0], %1, 0x989680;\n\t" \
            "@P1 bra.uni WAIT_DONEC_%=;\n\t" \
            "bra.uni WAIT_LOOPC_%=;\n\t" \
            "WAIT_DONEC_%=:\n\t}" \
            :: "r"(_mbar), "r"(_parity) : "memory"); \
    } \
} while (0)

#if TC_OK
#define TCGEN05_ALLOC(smem_result_addr, nCols) \
    asm volatile("tcgen05.alloc.cta_group::1.sync.aligned.shared::cta.b32 [%0], %1;" \
        :: "r"((uint32_t)(smem_result_addr)), "r"((uint32_t)(nCols)) : "memory")
#define TCGEN05_DEALLOC(tmem_addr, nCols) \
    asm volatile("tcgen05.dealloc.cta_group::1.sync.aligned.b32 %0, %1;" \
        :: "r"(tmem_addr), "r"((uint32_t)(nCols)))
#define TCGEN05_RELINQUISH() \
    asm volatile("tcgen05.relinquish_alloc_permit.cta_group::1.sync.aligned;")
#define TCGEN05_COMMIT(mbar) \
    asm volatile("tcgen05.commit.cta_group::1.mbarrier::arrive::one.shared::cluster.b64 [%0];" \
        :: "r"((uint32_t)(mbar)) : "memory")

#define TCGEN05_ALLOC_CG2(smem_result_addr, nCols) \
    asm volatile("tcgen05.alloc.cta_group::2.sync.aligned.shared::cta.b32 [%0], %1;" \
        :: "r"((uint32_t)(smem_result_addr)), "r"((uint32_t)(nCols)) : "memory")
#define TCGEN05_DEALLOC_CG2(tmem_addr, nCols) \
    asm volatile("tcgen05.dealloc.cta_group::2.sync.aligned.b32 %0, %1;" \
        :: "r"(tmem_addr), "r"((uint32_t)(nCols)))
#define TCGEN05_RELINQUISH_CG2() \
    asm volatile("tcgen05.relinquish_alloc_permit.cta_group::2.sync.aligned;")
#define TCGEN05_COMMIT_MC_CG2(mbar, mask) \
    asm volatile("tcgen05.commit.cta_group::2.mbarrier::arrive::one.shared::cluster.multicast::cluster.b64 [%0], %1;" \
        :: "r"((uint32_t)(mbar)), "h"((uint16_t)(mask)) : "memory")

#define TCGEN05_FENCE_AFTER() \
    asm volatile("tcgen05.fence::after_thread_sync;" ::: "memory")
#define TCGEN05_WAIT_LD() \
    asm volatile("tcgen05.wait::ld.sync.aligned;" ::: "memory")
#define FENCE_PROXY_ASYNC() \
    asm volatile("fence.proxy.async.shared::cta;" ::: "memory")
#define CLUSTER_SYNC() do { \
    asm volatile("barrier.cluster.arrive.aligned;" ::: "memory"); \
    asm volatile("barrier.cluster.wait.aligned;" ::: "memory"); } while (0)
#define MBARRIER_ARRIVE_RANK0(local_mbar_addr) \
    asm volatile("{\n\t.reg .b32 remAddr32;\n\t" \
        "mapa.shared::cluster.u32 remAddr32, %0, 0;\n\t" \
        "mbarrier.arrive.shared::cluster.b64 _, [remAddr32];\n\t}" \
        :: "r"((uint32_t)(local_mbar_addr)) : "memory")

#define TCGEN05_LD_32X32B_X32(r, tmem_addr) \
    asm volatile( \
        "tcgen05.ld.sync.aligned.32x32b.x32.b32 " \
        "{%0, %1, %2, %3, %4, %5, %6, %7, " \
        " %8, %9, %10, %11, %12, %13, %14, %15, " \
        " %16, %17, %18, %19, %20, %21, %22, %23, " \
        " %24, %25, %26, %27, %28, %29, %30, %31}, [%32];" \
        : "=r"((r)[0]),  "=r"((r)[1]),  "=r"((r)[2]),  "=r"((r)[3]), \
          "=r"((r)[4]),  "=r"((r)[5]),  "=r"((r)[6]),  "=r"((r)[7]), \
          "=r"((r)[8]),  "=r"((r)[9]),  "=r"((r)[10]), "=r"((r)[11]), \
          "=r"((r)[12]), "=r"((r)[13]), "=r"((r)[14]), "=r"((r)[15]), \
          "=r"((r)[16]), "=r"((r)[17]), "=r"((r)[18]), "=r"((r)[19]), \
          "=r"((r)[20]), "=r"((r)[21]), "=r"((r)[22]), "=r"((r)[23]), \
          "=r"((r)[24]), "=r"((r)[25]), "=r"((r)[26]), "=r"((r)[27]), \
          "=r"((r)[28]), "=r"((r)[29]), "=r"((r)[30]), "=r"((r)[31]) \
        : "r"(tmem_addr))

__device__ __forceinline__ void mma_tf32(uint32_t d, uint64_t ad, uint64_t bd,
                                         uint32_t idesc, uint32_t en)
{
    asm volatile(
        "{\n\t"
        ".reg .pred p;\n\t"
        "setp.ne.u32 p, %5, 0;\n\t"
        "tcgen05.mma.cta_group::1.kind::tf32 [%0], %1, %2, %3, {%4, %4, %4, %4}, p;\n\t"
        "}"
        :: "r"(d), "l"(ad), "l"(bd), "r"(idesc), "r"(0u), "r"(en)
        : "memory");
}
__device__ __forceinline__ void mma_tf32_cg2(uint32_t d, uint64_t ad, uint64_t bd,
                                             uint32_t idesc, uint32_t en)
{
    asm volatile(
        "{\n\t"
        ".reg .pred p;\n\t"
        "setp.ne.u32 p, %5, 0;\n\t"
        "tcgen05.mma.cta_group::2.kind::tf32 [%0], %1, %2, %3, "
        "{%4, %4, %4, %4, %4, %4, %4, %4}, p;\n\t"
        "}"
        :: "r"(d), "l"(ad), "l"(bd), "r"(idesc), "r"(0u), "r"(en)
        : "memory");
}
#endif // TC_OK

// ---------------------------------------------------------------------------
// NF4 dequant + folded rank-16 lora (R9 LDS-optimized version, unchanged)
// ---------------------------------------------------------------------------
__global__ __launch_bounds__(256)
void dequant_kernel(const int* __restrict__ codes,
                    const float* __restrict__ absmax,
                    const float* __restrict__ la,
                    const float* __restrict__ lb,
                    float* __restrict__ W)
{
    __shared__ float la_s[64][16];   // row k: chunk p stored at ((p + k/16)&3)
    __shared__ float lb_s[16][64];
    const int kc0 = blockIdx.x * 64;
    const int n0  = blockIdx.y * 64;
    const int t = threadIdx.x;

    {
        int rw = t >> 2, p = t & 3;
        float4 v = *(const float4*)(la + (size_t)(kc0 + rw) * RLORA + p * 4);
        int col = ((p + (rw >> 4)) & 3) * 4;
        *(float4*)&la_s[rw][col] = v;
    }
#pragma unroll
    for (int q = 0; q < 4; q++) {
        int idx = t + q * 256;
        int r = idx >> 6, nl = idx & 63;
        lb_s[r][nl] = lb[(size_t)r * Hd + n0 + nl];
    }
    __syncthreads();

    const int nloc = t >> 2;
    const int qd = t & 3;
    const int k0 = qd * 16;
    const int row = n0 + nloc;
    const size_t base = (size_t)row * Hd + kc0 + k0;
    const float am = absmax[base >> 6];

    float lbr[16];
#pragma unroll
    for (int r = 0; r < 16; r++) lbr[r] = lb_s[r][nloc];

    int4 cc[4];
#pragma unroll
    for (int q = 0; q < 4; q++) cc[q] = *(const int4*)(codes + base + q * 4);

    float lv[16];
#pragma unroll
    for (int i = 0; i < 16; i++) {
        int k = k0 + i;
        float4 a0 = *(float4*)&la_s[k][((0 + qd) & 3) * 4];
        float4 a1 = *(float4*)&la_s[k][((1 + qd) & 3) * 4];
        float4 a2 = *(float4*)&la_s[k][((2 + qd) & 3) * 4];
        float4 a3 = *(float4*)&la_s[k][((3 + qd) & 3) * 4];
        float s0 = a0.x * lbr[0]  + a0.y * lbr[1]  + a0.z * lbr[2]  + a0.w * lbr[3];
        float s1 = a1.x * lbr[4]  + a1.y * lbr[5]  + a1.z * lbr[6]  + a1.w * lbr[7];
        float s2 = a2.x * lbr[8]  + a2.y * lbr[9]  + a2.z * lbr[10] + a2.w * lbr[11];
        float s3 = a3.x * lbr[12] + a3.y * lbr[13] + a3.z * lbr[14] + a3.w * lbr[15];
        lv[i] = (s0 + s1) + (s2 + s3);
    }

    float* dst = W + base;
#pragma unroll
    for (int q = 0; q < 4; q++) {
        int4 c = cc[q];
        float4 o;
        o.x = tf32r(c_nf4[c.x & 15] * am + lv[q * 4 + 0]);
        o.y = tf32r(c_nf4[c.y & 15] * am + lv[q * 4 + 1]);
        o.z = tf32r(c_nf4[c.z & 15] * am + lv[q * 4 + 2]);
        o.w = tf32r(c_nf4[c.w & 15] * am + lv[q * 4 + 3]);
        *(float4*)(dst + q * 4) = o;
    }
}

// ---------------------------------------------------------------------------
// Round x (fp32 -> tf32) into A (flat copy)
// ---------------------------------------------------------------------------
__global__ void roundx_kernel(const float* __restrict__ x, float* __restrict__ Aa)
{
    size_t base = ((size_t)blockIdx.x * blockDim.x + threadIdx.x) * 4;
    if (base >= (size_t)NELEM) return;
    float4 v = *(const float4*)(x + base);
    *(float4*)(Aa + base) =
        make_float4(tf32r(v.x), tf32r(v.y), tf32r(v.z), tf32r(v.w));
}

// ---------------------------------------------------------------------------
// V transpose: Vt[d_global][k] = V[k][d_global]   (4096 x 1024)
// ---------------------------------------------------------------------------
__global__ void vt_kernel(const float* __restrict__ V, float* __restrict__ Vt)
{
    __shared__ float tile[32][33];
    int x0 = blockIdx.x * 32;
    int y0 = blockIdx.y * 32;
    for (int i = threadIdx.y; i < 32; i += 8)
        tile[i][threadIdx.x] = V[(size_t)(y0 + i) * Hd + x0 + threadIdx.x];
    __syncthreads();
    for (int i = threadIdx.y; i < 32; i += 8)
        Vt[(size_t)(x0 + i) * Sq + y0 + threadIdx.x] = tile[threadIdx.x][i];
}

// ---------------------------------------------------------------------------
// cg2 projection GEMM (R7 proven version, unchanged)
// ---------------------------------------------------------------------------
#if TC_OK
template<bool ROUND>
__global__ __launch_bounds__(256, 1) __cluster_dims__(2, 1, 1)
void proj_gemm_cg2(const float* __restrict__ A, const float* __restrict__ B,
                   const float* __restrict__ bias, float* __restrict__ C, int CK)
{
    extern __shared__ char smem[];
    const unsigned sbase = smem_u32(smem);
    constexpr int ASUB = 128 * 128;
    constexpr int BSUB = 128 * 128;
    constexpr int ABUF = 2 * ASUB;
    constexpr int BBUF = 2 * BSUB;
    constexpr unsigned ABUF0 = 1024;
    constexpr unsigned BBUF0 = 1024 + 2 * ABUF;
    constexpr uint32_t IDESC =
        (1u << 4) | (2u << 7) | (2u << 10) | ((256 / 8) << 17) | (16u << 24);

    const int tid = threadIdx.x, wid = tid >> 5, lane = tid & 31;
    const int rank = blockIdx.x & 1;
    const int pair = blockIdx.x >> 1;
    const int bm = pair * 256 + rank * 128;
    const int bn = blockIdx.y * 256;

    if (wid == 0) TCGEN05_ALLOC_CG2(sbase, 256);
    if (tid == 0) {
        MBARRIER_INIT(sbase + 16, 2);
        MBARRIER_INIT(sbase + 24, 2);
        MBARRIER_INIT(sbase + 32, 1);
        MBARRIER_INIT(sbase + 40, 1);
    }
    __syncthreads();
    unsigned tmem;
    asm volatile("ld.shared.b32 %0, [%1];" : "=r"(tmem) : "r"(sbase));
    if (wid == 0) TCGEN05_RELINQUISH_CG2();
    CLUSTER_SYNC();

    bool isel = false;
    if (wid == 0) isel = elect_one();

    auto load_chunk = [&](int c) {
        int b = c & 1;
        unsigned sA = sbase + ABUF0 + b * ABUF;
        unsigned sB = sbase + BBUF0 + b * BBUF;
        const float* Ab = A + (size_t)bm * Hd + c * 64;
#pragma unroll
        for (int l = 0; l < 8; l++) {
            int s = tid + l * 256;
            int sub = s >> 10, w = s & 1023;
            int r = w >> 3, i = w & 7;
            cpa16(sA + sub * ASUB + swz(r * 128 + i * 16),
                  Ab + (size_t)r * Hd + sub * 32 + i * 4);
        }
        const float* Bb = B + (size_t)(bn + rank * 128) * Hd + c * 64;
#pragma unroll
        for (int l = 0; l < 8; l++) {
            int s = tid + l * 256;
            int sub = s >> 10, w = s & 1023;
            int r = w >> 3, i = w & 7;
            cpa16(sB + sub * BSUB + swz(r * 128 + i * 16),
                  Bb + (size_t)r * Hd + sub * 32 + i * 4);
        }
        asm volatile("cp.async.commit_group;" ::: "memory");
    };

    load_chunk(0);
    load_chunk(1);

    for (int c = 0; c < CK; ++c) {
        int b = c & 1;
        if (c + 1 < CK) asm volatile("cp.async.wait_group 1;" ::: "memory");
        else            asm volatile("cp.async.wait_group 0;" ::: "memory");
        __syncthreads();
        if (tid == 0) {
            FENCE_PROXY_ASYNC();
            MBARRIER_ARRIVE_RANK0(sbase + 16 + 8 * b);
        }
        if (rank == 0 && isel) {
            MBARRIER_WAIT_PARITY_CL(sbase + 16 + 8 * b, (c >> 1) & 1);
#pragma unroll
            for (int j = 0; j < 2; j++) {
                uint64_t ad = MAKE_SMEM_DESC(sbase + ABUF0 + b * ABUF + j * ASUB);
                uint64_t bd = MAKE_SMEM_DESC(sbase + BBUF0 + b * BBUF + j * BSUB);
#pragma unroll
                for (int s = 0; s < 4; s++)
                    mma_tf32_cg2(tmem, ad + s * 2, bd + s * 2, IDESC,
                                 (c > 0 || j > 0 || s > 0) ? 1u : 0u);
            }
            TCGEN05_COMMIT_MC_CG2(sbase + 32 + 8 * b, 0x3);
        }
        if (c + 2 < CK) {
            MBARRIER_WAIT_PARITY(sbase + 32 + 8 * b, (c >> 1) & 1);
            load_chunk(c + 2);
        }
    }
    {
        int c = CK - 1, b = c & 1;
        MBARRIER_WAIT_PARITY(sbase + 32 + 8 * b, (c >> 1) & 1);
    }
    TCGEN05_FENCE_AFTER();

    if (wid < 4) {
        int row = bm + wid * 32 + lane;
#pragma unroll
        for (int nb = 0; nb < 8; nb++) {
            uint32_t r[32];
            TCGEN05_LD_32X32B_X32(r, tmem + nb * 32);
            TCGEN05_WAIT_LD();
            int col0 = bn + nb * 32;
            float v[32];
#pragma unroll
            for (int j = 0; j < 32; j++) {
                float d = __uint_as_float(r[j]) + bias[col0 + j];
                if (ROUND) d = tf32r(d);
                v[j] = d;
            }
            float4* dst = (float4*)(C + (size_t)row * Hd + col0);
#pragma unroll
            for (int q = 0; q < 8; q++)
                dst[q] = make_float4(v[4*q], v[4*q+1], v[4*q+2], v[4*q+3]);
        }
    }
    __syncthreads();
    CLUSTER_SYNC();
    if (wid == 0) TCGEN05_DEALLOC_CG2(tmem, 256);
    CLUSTER_SYNC();
}
#else
// generic fallback: plain FFMA tile 128x256 per CTA
template<bool ROUND>
__global__ __launch_bounds__(256, 1) __cluster_dims__(2, 1, 1)
void proj_gemm_cg2(const float* __restrict__ A, const float* __restrict__ B,
                   const float* __restrict__ bias, float* __restrict__ C, int CK)
{
    extern __shared__ char smem[];
    float* As = (float*)smem;
    float* Bs = (float*)(smem + 16 * 128 * 4);
    const int tid = threadIdx.x;
    const int rank = blockIdx.x & 1;
    const int bm = (blockIdx.x >> 1) * 256 + rank * 128;
    const int bn = blockIdx.y * 256;
    const int Kd = CK * 64;
    const int tx = tid & 15, ty = tid >> 4;
    float acc[8][16];
#pragma unroll
    for (int i = 0; i < 8; i++)
#pragma unroll
        for (int j = 0; j < 16; j++) acc[i][j] = 0.f;

    for (int k0 = 0; k0 < Kd; k0 += 16) {
#pragma unroll
        for (int l = 0; l < 2; l++) {
            int f = tid + l * 256;
            int r = f >> 2, c4 = f & 3;
            float4 v = *(const float4*)(A + (size_t)(bm + r) * Hd + k0 + c4 * 4);
            As[(c4 * 4 + 0) * 128 + r] = v.x; As[(c4 * 4 + 1) * 128 + r] = v.y;
            As[(c4 * 4 + 2) * 128 + r] = v.z; As[(c4 * 4 + 3) * 128 + r] = v.w;
        }
#pragma unroll
        for (int l = 0; l < 4; l++) {
            int f = tid + l * 256;
            int r = f >> 2, c4 = f & 3;
            float4 v = *(const float4*)(B + (size_t)(bn + r) * Hd + k0 + c4 * 4);
            Bs[(c4 * 4 + 0) * 256 + r] = v.x; Bs[(c4 * 4 + 1) * 256 + r] = v.y;
            Bs[(c4 * 4 + 2) * 256 + r] = v.z; Bs[(c4 * 4 + 3) * 256 + r] = v.w;
        }
        __syncthreads();
#pragma unroll
        for (int kk = 0; kk < 16; kk++) {
            float ar[8], br[16];
#pragma unroll
            for (int i = 0; i < 8; i++) ar[i] = As[kk * 128 + ty * 8 + i];
#pragma unroll
            for (int j = 0; j < 16; j++) br[j] = Bs[kk * 256 + tx * 16 + j];
#pragma unroll
            for (int i = 0; i < 8; i++)
#pragma unroll
                for (int j = 0; j < 16; j++)
                    acc[i][j] += ar[i] * br[j];
        }
        __syncthreads();
    }
#pragma unroll
    for (int i = 0; i < 8; i++) {
        int row = bm + ty * 8 + i;
#pragma unroll
        for (int j = 0; j < 16; j++) {
            int col = bn + tx * 16 + j;
            float d = acc[i][j] + bias[col];
            if (ROUND) d = tf32r(d);
            C[(size_t)row * Hd + col] = d;
        }
    }
}
#endif

// ---------------------------------------------------------------------------
// cg1 GEMM for attention (scores / PV) — R7 proven version, unchanged.
// MODE 1: C = D*scale + mask[row,col]   MODE 2: C = D
// ---------------------------------------------------------------------------
template<int NT, int MODE, bool ROUND>
__global__ __launch_bounds__(256, 1)
void tf32_gemm(const float* __restrict__ A, long lda, long zA,
               const float* __restrict__ B, long ldb, long zB,
               float* __restrict__ C, long ldc, long zC,
               const float* __restrict__ aux, int CK)
{
#if TC_OK
    extern __shared__ char smem[];
    const unsigned sbase = smem_u32(smem);
    constexpr int ASUB = 128 * 128;
    constexpr int BSUB = NT * 128;
    constexpr int ABUF = 2 * ASUB;
    constexpr int BBUF = 2 * BSUB;
    constexpr unsigned ABUF0 = 1024;
    constexpr unsigned BBUF0 = 1024 + 2 * ABUF;
    constexpr uint32_t IDESC =
        (1u << 4) | (2u << 7) | (2u << 10) | ((NT / 8) << 17) | (8u << 24);

    const int tid = threadIdx.x, wid = tid >> 5, lane = tid & 31;
    const int bm = blockIdx.y * 128, bn = blockIdx.x * NT, bz = blockIdx.z;
    const float* Az = A + (size_t)zA * bz;
    const float* Bz = B + (size_t)zB * bz;
    float*       Cz = C + (size_t)zC * bz;

    if (wid == 0) TCGEN05_ALLOC(sbase, 256);
    if (tid == 0) { MBARRIER_INIT(sbase + 16, 1); MBARRIER_INIT(sbase + 24, 1); }
    __syncthreads();
    unsigned tmem;
    asm volatile("ld.shared.b32 %0, [%1];" : "=r"(tmem) : "r"(sbase));
    if (wid == 0) TCGEN05_RELINQUISH();

    bool isel = false;
    if (wid == 0) isel = elect_one();

    auto load_chunk = [&](int c) {
        int b = c & 1;
        unsigned sA = sbase + ABUF0 + b * ABUF;
        unsigned sB = sbase + BBUF0 + b * BBUF;
        const float* Ab = Az + (size_t)bm * lda + c * 64;
#pragma unroll
        for (int l = 0; l < 8; l++) {
            int s = tid + l * 256;
            int sub = s >> 10, w = s & 1023;
            int r = w >> 3, i = w & 7;
            cpa16(sA + sub * ASUB + swz(r * 128 + i * 16),
                  Ab + (size_t)r * lda + sub * 32 + i * 4);
        }
        const float* Bb = Bz + (size_t)bn * ldb + c * 64;
#pragma unroll
        for (int l = 0; l < NT / 16; l++) {
            int s = tid + l * 256;
            int sub = s / (NT * 8), w = s % (NT * 8);
            int r = w >> 3, i = w & 7;
            cpa16(sB + sub * BSUB + swz(r * 128 + i * 16),
                  Bb + (size_t)r * ldb + sub * 32 + i * 4);
        }
        asm volatile("cp.async.commit_group;" ::: "memory");
    };

    load_chunk(0);
    load_chunk(1);

    for (int c = 0; c < CK; ++c) {
        int b = c & 1;
        if (c + 1 < CK) asm volatile("cp.async.wait_group 1;" ::: "memory");
        else            asm volatile("cp.async.wait_group 0;" ::: "memory");
        __syncthreads();
        if (isel) {
            FENCE_PROXY_ASYNC();
#pragma unroll
            for (int j = 0; j < 2; j++) {
                uint64_t ad = MAKE_SMEM_DESC(sbase + ABUF0 + b * ABUF + j * ASUB);
                uint64_t bd = MAKE_SMEM_DESC(sbase + BBUF0 + b * BBUF + j * BSUB);
#pragma unroll
                for (int s = 0; s < 4; s++)
                    mma_tf32(tmem, ad + s * 2, bd + s * 2, IDESC,
                             (c > 0 || j > 0 || s > 0) ? 1u : 0u);
            }
            TCGEN05_COMMIT(sbase + 16 + 8 * b);
        }
        if (c + 2 < CK) {
            MBARRIER_WAIT_PARITY(sbase + 16 + 8 * b, (c >> 1) & 1);
            load_chunk(c + 2);
        }
    }
    {
        int c = CK - 1, b = c & 1;
        MBARRIER_WAIT_PARITY(sbase + 16 + 8 * b, (c >> 1) & 1);
    }
    TCGEN05_FENCE_AFTER();

    if (wid < 4) {
        int row = bm + wid * 32 + lane;
#pragma unroll
        for (int nb = 0; nb < NT / 32; nb++) {
            uint32_t r[32];
            TCGEN05_LD_32X32B_X32(r, tmem + nb * 32);
            TCGEN05_WAIT_LD();
            int col0 = bn + nb * 32;
            float v[32];
#pragma unroll
            for (int j = 0; j < 32; j++) {
                float d = __uint_as_float(r[j]);
                if (MODE == 1) d = d * 0.08838834764831845f
                                   + aux[(size_t)row * Sq + col0 + j];
                if (ROUND) d = tf32r(d);
                v[j] = d;
            }
            float4* dst = (float4*)(Cz + (size_t)row * ldc + col0);
#pragma unroll
            for (int q = 0; q < 8; q++)
                dst[q] = make_float4(v[4*q], v[4*q+1], v[4*q+2], v[4*q+3]);
        }
    }
    __syncthreads();
    if (wid == 0) TCGEN05_DEALLOC(tmem, 256);

#else  // ------- generic-arch FFMA fallback -------------
    extern __shared__ char smem[];
    float* As = (float*)smem;
    float* Bs = (float*)(smem + 16 * 128 * 4);
    const int tid = threadIdx.x;
    const int bm = blockIdx.y * 128, bn = blockIdx.x * NT, bz = blockIdx.z;
    const float* Az = A + (size_t)zA * bz;
    const float* Bz = B + (size_t)zB * bz;
    float*       Cz = C + (size_t)zC * bz;
    const int Kd = CK * 64;
    const int tx = tid & 15, ty = tid >> 4;
    constexpr int JW = NT / 16;
    float acc[8][JW];
#pragma unroll
    for (int i = 0; i < 8; i++)
#pragma unroll
        for (int j = 0; j < JW; j++) acc[i][j] = 0.f;

    for (int k0 = 0; k0 < Kd; k0 += 16) {
#pragma unroll
        for (int l = 0; l < 2; l++) {
            int f = tid + l * 256;
            int r = f >> 2, c4 = f & 3;
            float4 v = *(const float4*)(Az + (size_t)(bm + r) * lda + k0 + c4 * 4);
            As[(c4 * 4 + 0) * 128 + r] = v.x; As[(c4 * 4 + 1) * 128 + r] = v.y;
            As[(c4 * 4 + 2) * 128 + r] = v.z; As[(c4 * 4 + 3) * 128 + r] = v.w;
        }
#pragma unroll
        for (int l = 0; l < NT / 64; l++) {
            int f = tid + l * 256;
            int r = f >> 2, c4 = f & 3;
            float4 v = *(const float4*)(Bz + (size_t)(bn + r) * ldb + k0 + c4 * 4);
            Bs[(c4 * 4 + 0) * NT + r] = v.x; Bs[(c4 * 4 + 1) * NT + r] = v.y;
            Bs[(c4 * 4 + 2) * NT + r] = v.z; Bs[(c4 * 4 + 3) * NT + r] = v.w;
        }
        __syncthreads();
#pragma unroll
        for (int kk = 0; kk < 16; kk++) {
            float ar[8], br[JW];
#pragma unroll
            for (int i = 0; i < 8; i++) ar[i] = As[kk * 128 + ty * 8 + i];
#pragma unroll
            for (int j = 0; j < JW; j++) br[j] = Bs[kk * NT + tx * JW + j];
#pragma unroll
            for (int i = 0; i < 8; i++)
#pragma unroll
                for (int j = 0; j < JW; j++)
                    acc[i][j] += ar[i] * br[j];
        }
        __syncthreads();
    }
#pragma unroll
    for (int i = 0; i < 8; i++) {
        int row = bm + ty * 8 + i;
#pragma unroll
        for (int j = 0; j < JW; j++) {
            int col = bn + tx * JW + j;
            float d = acc[i][j];
            if (MODE == 1) d = d * 0.08838834764831845f
                               + aux[(size_t)row * Sq + col];
            if (ROUND) d = tf32r(d);
            Cz[(size_t)row * ldc + col] = d;
        }
    }
#endif
}

// ---------------------------------------------------------------------------
// Single-pass row softmax (unchanged)
// ---------------------------------------------------------------------------
__global__ void softmax_kernel(float* __restrict__ S)
{
    size_t row = blockIdx.x;
    float4* p = (float4*)(S + row * Sq);
    int tid = threadIdx.x;
    float4 v = p[tid];
    __shared__ float red[8];

    float m = fmaxf(fmaxf(v.x, v.y), fmaxf(v.z, v.w));
#pragma unroll
    for (int o = 16; o > 0; o >>= 1) m = fmaxf(m, __shfl_xor_sync(~0u, m, o));
    if ((tid & 31) == 0) red[tid >> 5] = m;
    __syncthreads();
    m = red[0];
#pragma unroll
    for (int w = 1; w < 8; w++) m = fmaxf(m, red[w]);
    __syncthreads();

    float4 e;
    e.x = expf(v.x - m); e.y = expf(v.y - m);
    e.z = expf(v.z - m); e.w = expf(v.w - m);
    float s = (e.x + e.y) + (e.z + e.w);
#pragma unroll
    for (int o = 16; o > 0; o >>= 1) s += __shfl_xor_sync(~0u, s, o);
    if ((tid & 31) == 0) red[tid >> 5] = s;
    __syncthreads();
    s = red[0];
#pragma unroll
    for (int w = 1; w < 8; w++) s += red[w];
    float inv = 1.0f / s;
    p[tid] = make_float4(tf32r(e.x * inv), tf32r(e.y * inv),
                         tf32r(e.z * inv), tf32r(e.w * inv));
}

// ---------------------------------------------------------------------------
// Exact rank-k selection, 2 sweep passes (was 3):
//   pass 1: 11-bit level-1 histogram, warp-aggregated smem atomics.
//   pass 2: for level-1-matching elements, histogram 11-bit level-2 (smem)
//           AND the full remaining 21 bits into g_big (global, scattered).
//   fin:    pick b1, b2 from h1/h2; pick b3 directly from the 1024-entry
//           g_big slice at (b2<<10). No third data sweep.
// Zero-mass aggregated per block. Semantics identical to the 3-pass radix.
// ---------------------------------------------------------------------------
__device__ __forceinline__ void block_pick(const unsigned* __restrict__ h,
                                           unsigned long long k,
                                           unsigned* sps, unsigned long long* spr,
                                           unsigned& bin, unsigned long long& krem)
{
    int t = threadIdx.x;
    unsigned v[8]; unsigned s = 0;
#pragma unroll
    for (int i = 0; i < 8; i++) { v[i] = h[t * 8 + i]; s += v[i]; }
    sps[t] = s;
    __syncthreads();
    if (t == 0) {
        unsigned long long cum = 0; int ct = 0;
        while (ct < 255 && cum + sps[ct] < k) { cum += sps[ct]; ct++; }
        spr[0] = (unsigned long long)ct; spr[1] = k - cum;
    }
    __syncthreads();
    if (t == (int)spr[0]) {
        unsigned long long kk = spr[1]; int b = 7;
#pragma unroll
        for (int i = 0; i < 8; i++) {
            if (kk <= v[i]) { b = i; break; }
            kk -= v[i];
        }
        spr[0] = (unsigned long long)(t * 8 + b); spr[1] = kk;
    }
    __syncthreads();
    bin = (unsigned)spr[0]; krem = spr[1];
    __syncthreads();
}

__global__ void sel_clear0()
{
    int t = blockIdx.x * blockDim.x + threadIdx.x;   // grid 48x256 = 12288
    if (t < 6 * 2048) { ((unsigned*)g_h1)[t] = 0; ((unsigned*)g_h2)[t] = 0; }
}

__global__ void big_clear()
{
    size_t i = (size_t)blockIdx.x * blockDim.x + threadIdx.x;  // 12288x256
    if (i < ((size_t)6 * BIGN) / 4)
        ((uint4*)g_big)[i] = make_uint4(0, 0, 0, 0);
}

__global__ void sel_h1_all(SelArgs a)
{
    int z = blockIdx.z;
    const float* data = a.d[z];
    size_t n4 = (size_t)a.n[z] >> 2;
    __shared__ unsigned sh[2048];
    for (int i = threadIdx.x; i < 2048; i += 256) sh[i] = 0;
    __syncthreads();
    const int lane = threadIdx.x & 31;
    size_t stride = (size_t)gridDim.x * 256;
    for (size_t f = (size_t)blockIdx.x * 256 + threadIdx.x; f < n4; f += stride) {
        float4 d = *(const float4*)(data + (f << 2));
        unsigned uu[4] = { __float_as_uint(d.x), __float_as_uint(d.y),
                           __float_as_uint(d.z), __float_as_uint(d.w) };
#pragma unroll
        for (int j = 0; j < 4; j++) {
            unsigned bin = (uu[j] & 0x7FFFFFFFu) >> 21;
            unsigned m = __match_any_sync(0xFFFFFFFFu, bin);
            if ((__ffs(m) - 1) == lane) atomicAdd(&sh[bin], (unsigned)__popc(m));
        }
    }
    __syncthreads();
    for (int i = threadIdx.x; i < 2048; i += 256)
        if (sh[i]) atomicAdd(&g_h1[z][i], sh[i]);
}

__global__ void sel_h23_all(SelArgs a)
{
    int z = blockIdx.z;
    const float* data = a.d[z];
    size_t n4 = (size_t)a.n[z] >> 2;
    __shared__ unsigned sh2[2048];
    __shared__ unsigned sps[256]; __shared__ unsigned long long spr[2];
    __shared__ unsigned zsh;
    unsigned b1; unsigned long long kr;
    block_pick(g_h1[z], a.k[z], sps, spr, b1, kr);
    for (int i = threadIdx.x; i < 2048; i += 256) sh2[i] = 0;
    if (threadIdx.x == 0) zsh = 0;
    __syncthreads();
    const unsigned pref = b1 << 21;
    const int lane = threadIdx.x & 31;
    unsigned zc = 0;
    size_t stride = (size_t)gridDim.x * 256;
    for (size_t f = (size_t)blockIdx.x * 256 + threadIdx.x; f < n4; f += stride) {
        float4 d = *(const float4*)(data + (f << 2));
        unsigned uu[4] = { __float_as_uint(d.x), __float_as_uint(d.y),
                           __float_as_uint(d.z), __float_as_uint(d.w) };
#pragma unroll
        for (int j = 0; j < 4; j++) {
            unsigned u = uu[j] & 0x7FFFFFFFu;
            bool mt = (u & 0xFFE00000u) == pref;
            bool act = mt && (u != 0u);
            if (mt && u == 0u) zc++;
            unsigned am = __ballot_sync(0xFFFFFFFFu, act);
            if (act) {
                unsigned key = u & 0x1FFFFFu;
                unsigned m = __match_any_sync(am, key);
                if ((__ffs(m) - 1) == lane) {
                    unsigned cnt = (unsigned)__popc(m);
                    atomicAdd(&sh2[key >> 10], cnt);
                    atomicAdd(&g_big[z][key], cnt);
                }
            }
        }
    }
    if (zc) atomicAdd(&zsh, zc);
    __syncthreads();
    if (threadIdx.x == 0 && zsh) {
        atomicAdd(&sh2[0], zsh);
        atomicAdd(&g_big[z][0], zsh);
    }
    __syncthreads();
    for (int i = threadIdx.x; i < 2048; i += 256)
        if (sh2[i]) atomicAdd(&g_h2[z][i], sh2[i]);
}

__global__ void sel_fin_all(SelArgs a, float* __restrict__ out)
{
    int z = blockIdx.x;                        // 6 blocks
    __shared__ unsigned sps[256]; __shared__ unsigned long long spr[2];
    unsigned b1, b2, b3; unsigned long long k2, k3;
    block_pick(g_h1[z], a.k[z], sps, spr, b1, k2);
    block_pick(g_h2[z], k2,     sps, spr, b2, k3);
    {   // level-3 pick over the 1024-entry g_big slice at (b2<<10)
        int t = threadIdx.x;
        const unsigned* slice = &g_big[z][(size_t)b2 << 10];
        unsigned v[4]; unsigned s = 0;
#pragma unroll
        for (int i = 0; i < 4; i++) { v[i] = slice[t * 4 + i]; s += v[i]; }
        sps[t] = s;
        __syncthreads();
        if (t == 0) {
            unsigned long long cum = 0; int ct = 0;
            while (ct < 255 && cum + sps[ct] < k3) { cum += sps[ct]; ct++; }
            spr[0] = (unsigned long long)ct; spr[1] = k3 - cum;
        }
        __syncthreads();
        if (t == (int)spr[0]) {
            unsigned long long kk = spr[1]; int b = 3;
#pragma unroll
            for (int i = 0; i < 4; i++) {
                if (kk <= v[i]) { b = i; break; }
                kk -= v[i];
            }
            spr[0] = (unsigned long long)(t * 4 + b);
        }
        __syncthreads();
        b3 = (unsigned)spr[0];
        __syncthreads();
    }
    // re-zero h1/h2 (g_big is recleared by big_clear at launch start)
    for (int i = threadIdx.x; i < 2048; i += 256) { g_h1[z][i] = 0; g_h2[z][i] = 0; }
    if (threadIdx.x == 0)
        out[z] = __uint_as_float((b1 << 21) | (b2 << 10) | b3);
}

// ---------------------------------------------------------------------------
// Host orchestration
// ---------------------------------------------------------------------------
extern "C" void kernel_launch(void* const* d_in, const int* in_sizes, int n_in,
                              void* d_out, int out_size)
{
    const float* x    = (const float*)d_in[0];
    const int*   codes[4];
    const float *amax[4], *bias[4], *la[4], *lb[4];
    for (int p = 0; p < 4; p++) {
        codes[p] = (const int*)  d_in[1 + p * 5 + 0];
        amax[p]  = (const float*)d_in[1 + p * 5 + 1];
        bias[p]  = (const float*)d_in[1 + p * 5 + 2];
        la[p]    = (const float*)d_in[1 + p * 5 + 3];
        lb[p]    = (const float*)d_in[1 + p * 5 + 4];
    }
    const float* mask = (const float*)d_in[21];
    float* out = (float*)d_out;

    float *pAa, *pBa, *pQ, *pK, *pV, *pVt, *pAttn;
    cudaGetSymbolAddress((void**)&pAa,   g_Aaug);
    cudaGetSymbolAddress((void**)&pBa,   g_Baug);
    cudaGetSymbolAddress((void**)&pQ,    g_q);
    cudaGetSymbolAddress((void**)&pK,    g_k);
    cudaGetSymbolAddress((void**)&pV,    g_v);
    cudaGetSymbolAddress((void**)&pVt,   g_vt);
    cudaGetSymbolAddress((void**)&pAttn, g_attn);

    const int SMCG2 = 1024 + 4 * (2 * 128 * 128);                        // 132096
    const int SM256 = 1024 + 2 * (2 * 128 * 128) + 2 * (2 * 256 * 128);  // 197632
    const int SM128 = 1024 + 2 * (2 * 128 * 128) + 2 * (2 * 128 * 128);  // 132096
    cudaFuncSetAttribute(proj_gemm_cg2<true>,
        cudaFuncAttributeMaxDynamicSharedMemorySize, SMCG2);
    cudaFuncSetAttribute(proj_gemm_cg2<false>,
        cudaFuncAttributeMaxDynamicSharedMemorySize, SMCG2);
    cudaFuncSetAttribute(tf32_gemm<256, 1, false>,
        cudaFuncAttributeMaxDynamicSharedMemorySize, SM256);
    cudaFuncSetAttribute(tf32_gemm<128, 2, true>,
        cudaFuncAttributeMaxDynamicSharedMemorySize, SM128);

    const int CKP = Hd / 64;        // 64 chunks for projections

    big_clear <<<12288, 256>>>();
    sel_clear0<<<48, 256>>>();
    roundx_kernel<<<NELEM / 4 / 256, 256>>>(x, pAa);

    // --- Q, K, V projections (cg2 pair tiles, lora folded in weights) ---
    float* qkv[3] = { pQ, pK, pV };
    for (int p = 0; p < 3; p++) {
        dequant_kernel<<<dim3(64, 64), 256>>>(codes[p], amax[p], la[p], lb[p], pBa);
        proj_gemm_cg2<true><<<dim3(8, 16, 1), 256, SMCG2>>>(
            pAa, pBa, bias[p], qkv[p], CKP);
    }

    // --- Attention ---
    tf32_gemm<256, 1, false><<<dim3(4, 8, NHEAD), 256, SM256>>>(
        pQ, Hd, HDIM, pK, Hd, HDIM, pAttn, Sq, (long)Sq * Sq, mask, HDIM / 64);
    softmax_kernel<<<NHEAD * Sq, 256>>>(pAttn);
    vt_kernel<<<dim3(Hd / 32, Sq / 32), dim3(32, 8)>>>(pV, pVt);
    tf32_gemm<128, 2, true><<<dim3(1, 8, NHEAD), 256, SM128>>>(
        pAttn, Sq, (long)Sq * Sq, pVt, Sq, (long)HDIM * Sq,
        pAa, Hd, HDIM, nullptr, Sq / 64);

    // --- Output projection -> d_out ---
    dequant_kernel<<<dim3(64, 64), 256>>>(codes[3], amax[3], la[3], lb[3], pBa);
    proj_gemm_cg2<false><<<dim3(8, 16, 1), 256, SMCG2>>>(
        pAa, pBa, bias[3], out, CKP);

    // --- kth values: [x, qh, kh, vh, a, o] (batched; 2 sweeps + fin) ---
    SelArgs sa;
    sa.d[0] = x;     sa.n[0] = NELEM; sa.k[0] = NELEM / 2;
    sa.d[1] = pQ;    sa.n[1] = NELEM; sa.k[1] = NELEM / 2;
    sa.d[2] = pK;    sa.n[2] = NELEM; sa.k[2] = NELEM / 2;
    sa.d[3] = pV;    sa.n[3] = NELEM; sa.k[3] = NELEM / 2;
    sa.d[4] = pAttn; sa.n[4] = AELEM; sa.k[4] = AELEM / 2;
    sa.d[5] = pAa;   sa.n[5] = NELEM; sa.k[5] = NELEM / 2;

    sel_h1_all <<<dim3(512, 1, 6), 256>>>(sa);
    sel_h23_all<<<dim3(512, 1, 6), 256>>>(sa);
    sel_fin_all<<<6, 256>>>(sa, out + NELEM);
}

// round 14
// speedup vs baseline: 1.1177x; 1.1177x over previous
#include <cuda_runtime.h>
#include <cstdint>
#include <cstddef>

// ---------------------------------------------------------------------------
// Problem constants
// ---------------------------------------------------------------------------
#define Sq      1024
#define Hd      4096
#define NHEAD   32
#define HDIM    128
#define RLORA   16
#define NELEM   (Sq * Hd)                   // 4194304
#define WELEM   (Hd * Hd)                   // 16777216
#define AELEM   ((size_t)NHEAD * Sq * Sq)   // 33554432

// Arch-specific (sm_103a) feature gate.
#if defined(__CUDA_ARCH_FEAT_SM103_ALL) || defined(__CUDA_ARCH_FEAT_SM100_ALL) || \
    defined(__CUDA_ARCH_FEAT_SM101_ALL)
#define TC_OK 1
#else
#define TC_OK 0
#endif

// ---------------------------------------------------------------------------
// Device scratch (static: no allocation allowed)
// ---------------------------------------------------------------------------
__device__ float g_Aaug[NELEM];               // rounded A (x, later attn out)
__device__ float g_Baug[WELEM];               // dequant W + folded lora
__device__ float g_q[NELEM];
__device__ float g_k[NELEM];
__device__ float g_v[NELEM];
__device__ float g_vt[NELEM];                 // V transposed: [4096 d][1024 k]
__device__ float g_attn[AELEM];               // scores -> probs (tf32-rounded)

// selection state (per-tensor histograms, 6 tensors)
__device__ unsigned g_h1[6][2048], g_h2[6][2048], g_h3[6][1024];

struct SelArgs {
    const float*       d[6];
    unsigned long long n[6];
    unsigned long long k[6];
};

__constant__ float c_nf4[16] = {
    -1.0f, -0.6961928009986877f, -0.5250730514526367f, -0.39491748809814453f,
    -0.28444138169288635f, -0.18477343022823334f, -0.09105003625154495f, 0.0f,
    0.07958029955625534f, 0.16093020141124725f, 0.24611230194568634f,
    0.33791524171829224f, 0.4407098591327667f, 0.5626170039176941f,
    0.7229568362236023f, 1.0f };

// ---------------------------------------------------------------------------
// PTX helpers
// ---------------------------------------------------------------------------
__device__ __forceinline__ uint32_t smem_u32(const void* p) {
    uint32_t a;
    asm("{ .reg .u64 t; cvta.to.shared.u64 t, %1; cvt.u32.u64 %0, t; }"
        : "=r"(a) : "l"(p));
    return a;
}
__device__ __forceinline__ bool elect_one() {
    uint32_t pred;
    asm volatile("{\n\t.reg .pred p;\n\telect.sync _|p, 0xFFFFFFFF;\n\t"
                 "selp.b32 %0, 1, 0, p;\n\t}" : "=r"(pred));
    return pred != 0;
}
__device__ __forceinline__ float tf32r(float v) {
    unsigned u;
    asm("cvt.rna.tf32.f32 %0, %1;" : "=r"(u) : "f"(v));
    return __uint_as_float(u);
}
__device__ __forceinline__ unsigned swz(unsigned off) {   // SW128 swizzle
    return off ^ ((off >> 3) & 0x70);
}
__device__ __forceinline__ void cpa16(unsigned dst, const void* src) {
    asm volatile("cp.async.cg.shared.global [%0], [%1], 16;"
                 :: "r"(dst), "l"(src));
}

static constexpr uint64_t SMEM_DESC_BASE_SW128 =
    (uint64_t(2)  << 61) | (uint64_t(1) << 46) |
    (uint64_t(64) << 32) | (uint64_t(1) << 16);
#define MAKE_SMEM_DESC(base_addr) \
    (SMEM_DESC_BASE_SW128 | ((uint64_t)((base_addr) >> 4) & 0x3FFF))

#define MBARRIER_INIT(mbar, count) \
    asm volatile("mbarrier.init.shared.b64 [%0], %1;" \
        :: "r"((uint32_t)(mbar)), "r"((uint32_t)(count)) : "memory")

#define MBARRIER_WAIT_PARITY(mbar_smem_addr, phase_parity) do { \
    uint32_t _mbar = (uint32_t)(mbar_smem_addr); \
    uint32_t _parity = (uint32_t)(phase_parity); \
    uint32_t _done; \
    asm volatile("{\n\t.reg .pred p;\n\t" \
        "mbarrier.try_wait.parity.acquire.cta.shared::cta.b64 p, [%1], %2;\n\t" \
        "selp.b32 %0, 1, 0, p;\n\t}" \
        : "=r"(_done) : "r"(_mbar), "r"(_parity) : "memory"); \
    if (!_done) { \
        asm volatile("{\n\t.reg .pred P1;\n\t" \
            "WAIT_LOOP_%=:\n\t" \
            "mbarrier.try_wait.parity.acquire.cta.shared::cta.b64 P1, [%0], %1, 0x989680;\n\t" \
            "@P1 bra.uni WAIT_DONE_%=;\n\t" \
            "bra.uni WAIT_LOOP_%=;\n\t" \
            "WAIT_DONE_%=:\n\t}" \
            :: "r"(_mbar), "r"(_parity) : "memory"); \
    } \
} while (0)

// cluster-scope acquire variant (waiter side of a cross-CTA release-arrive)
#define MBARRIER_WAIT_PARITY_CL(mbar_smem_addr, phase_parity) do { \
    uint32_t _mbar = (uint32_t)(mbar_smem_addr); \
    uint32_t _parity = (uint32_t)(phase_parity); \
    uint32_t _done; \
    asm volatile("{\n\t.reg .pred p;\n\t" \
        "mbarrier.try_wait.parity.acquire.cluster.shared::cta.b64 p, [%1], %2;\n\t" \
        "selp.b32 %0, 1, 0, p;\n\t}" \
        : "=r"(_done) : "r"(_mbar), "r"(_parity) : "memory"); \
    if (!_done) { \
        asm volatile("{\n\t.reg .pred P1;\n\t" \
            "WAIT_LOOPC_%=:\n\t" \
            "mbarrier.try_wait.parity.acquire.cluster.shared::cta.b64 P1, [%0], %1, 0x989680;\n\t" \
            "@P1 bra.uni WAIT_DONEC_%=;\n\t" \
            "bra.uni WAIT_LOOPC_%=;\n\t" \
            "WAIT_DONEC_%=:\n\t}" \
            :: "r"(_mbar), "r"(_parity) : "memory"); \
    } \
} while (0)

#if TC_OK
#define TCGEN05_ALLOC(smem_result_addr, nCols) \
    asm volatile("tcgen05.alloc.cta_group::1.sync.aligned.shared::cta.b32 [%0], %1;" \
        :: "r"((uint32_t)(smem_result_addr)), "r"((uint32_t)(nCols)) : "memory")
#define TCGEN05_DEALLOC(tmem_addr, nCols) \
    asm volatile("tcgen05.dealloc.cta_group::1.sync.aligned.b32 %0, %1;" \
        :: "r"(tmem_addr), "r"((uint32_t)(nCols)))
#define TCGEN05_RELINQUISH() \
    asm volatile("tcgen05.relinquish_alloc_permit.cta_group::1.sync.aligned;")
#define TCGEN05_COMMIT(mbar) \
    asm volatile("tcgen05.commit.cta_group::1.mbarrier::arrive::one.shared::cluster.b64 [%0];" \
        :: "r"((uint32_t)(mbar)) : "memory")

#define TCGEN05_ALLOC_CG2(smem_result_addr, nCols) \
    asm volatile("tcgen05.alloc.cta_group::2.sync.aligned.shared::cta.b32 [%0], %1;" \
        :: "r"((uint32_t)(smem_result_addr)), "r"((uint32_t)(nCols)) : "memory")
#define TCGEN05_DEALLOC_CG2(tmem_addr, nCols) \
    asm volatile("tcgen05.dealloc.cta_group::2.sync.aligned.b32 %0, %1;" \
        :: "r"(tmem_addr), "r"((uint32_t)(nCols)))
#define TCGEN05_RELINQUISH_CG2() \
    asm volatile("tcgen05.relinquish_alloc_permit.cta_group::2.sync.aligned;")
#define TCGEN05_COMMIT_MC_CG2(mbar, mask) \
    asm volatile("tcgen05.commit.cta_group::2.mbarrier::arrive::one.shared::cluster.multicast::cluster.b64 [%0], %1;" \
        :: "r"((uint32_t)(mbar)), "h"((uint16_t)(mask)) : "memory")

#define TCGEN05_FENCE_AFTER() \
    asm volatile("tcgen05.fence::after_thread_sync;" ::: "memory")
#define TCGEN05_WAIT_LD() \
    asm volatile("tcgen05.wait::ld.sync.aligned;" ::: "memory")
#define FENCE_PROXY_ASYNC() \
    asm volatile("fence.proxy.async.shared::cta;" ::: "memory")
#define CLUSTER_SYNC() do { \
    asm volatile("barrier.cluster.arrive.aligned;" ::: "memory"); \
    asm volatile("barrier.cluster.wait.aligned;" ::: "memory"); } while (0)
#define MBARRIER_ARRIVE_RANK0(local_mbar_addr) \
    asm volatile("{\n\t.reg .b32 remAddr32;\n\t" \
        "mapa.shared::cluster.u32 remAddr32, %0, 0;\n\t" \
        "mbarrier.arrive.shared::cluster.b64 _, [remAddr32];\n\t}" \
        :: "r"((uint32_t)(local_mbar_addr)) : "memory")

#define TCGEN05_LD_32X32B_X32(r, tmem_addr) \
    asm volatile( \
        "tcgen05.ld.sync.aligned.32x32b.x32.b32 " \
        "{%0, %1, %2, %3, %4, %5, %6, %7, " \
        " %8, %9, %10, %11, %12, %13, %14, %15, " \
        " %16, %17, %18, %19, %20, %21, %22, %23, " \
        " %24, %25, %26, %27, %28, %29, %30, %31}, [%32];" \
        : "=r"((r)[0]),  "=r"((r)[1]),  "=r"((r)[2]),  "=r"((r)[3]), \
          "=r"((r)[4]),  "=r"((r)[5]),  "=r"((r)[6]),  "=r"((r)[7]), \
          "=r"((r)[8]),  "=r"((r)[9]),  "=r"((r)[10]), "=r"((r)[11]), \
          "=r"((r)[12]), "=r"((r)[13]), "=r"((r)[14]), "=r"((r)[15]), \
          "=r"((r)[16]), "=r"((r)[17]), "=r"((r)[18]), "=r"((r)[19]), \
          "=r"((r)[20]), "=r"((r)[21]), "=r"((r)[22]), "=r"((r)[23]), \
          "=r"((r)[24]), "=r"((r)[25]), "=r"((r)[26]), "=r"((r)[27]), \
          "=r"((r)[28]), "=r"((r)[29]), "=r"((r)[30]), "=r"((r)[31]) \
        : "r"(tmem_addr))

__device__ __forceinline__ void mma_tf32(uint32_t d, uint64_t ad, uint64_t bd,
                                         uint32_t idesc, uint32_t en)
{
    asm volatile(
        "{\n\t"
        ".reg .pred p;\n\t"
        "setp.ne.u32 p, %5, 0;\n\t"
        "tcgen05.mma.cta_group::1.kind::tf32 [%0], %1, %2, %3, {%4, %4, %4, %4}, p;\n\t"
        "}"
        :: "r"(d), "l"(ad), "l"(bd), "r"(idesc), "r"(0u), "r"(en)
        : "memory");
}
__device__ __forceinline__ void mma_tf32_cg2(uint32_t d, uint64_t ad, uint64_t bd,
                                             uint32_t idesc, uint32_t en)
{
    asm volatile(
        "{\n\t"
        ".reg .pred p;\n\t"
        "setp.ne.u32 p, %5, 0;\n\t"
        "tcgen05.mma.cta_group::2.kind::tf32 [%0], %1, %2, %3, "
        "{%4, %4, %4, %4, %4, %4, %4, %4}, p;\n\t"
        "}"
        :: "r"(d), "l"(ad), "l"(bd), "r"(idesc), "r"(0u), "r"(en)
        : "memory");
}
#endif // TC_OK

// ---------------------------------------------------------------------------
// NF4 dequant + folded rank-16 lora, v3 (outer-product microtile):
//   la transposed in smem (la_t[r][k]); thread (tn=t>>4, tk=t&15) owns a
//   4n x 4k microtile. Per r: 1 LDS128 of la + 1 broadcast LDS128 of lb +
//   16 FMA. 32 LDS128/thread total (half of v2); warp-contiguous k makes
//   codes loads / W stores 256B-coalesced.
// ---------------------------------------------------------------------------
__global__ __launch_bounds__(256)
void dequant_kernel(const int* __restrict__ codes,
                    const float* __restrict__ absmax,
                    const float* __restrict__ la,
                    const float* __restrict__ lb,
                    float* __restrict__ W)
{
    __shared__ float la_t[16][68];               // [r][k], 16B-aligned rows
    __shared__ float lb_s[16][64];               // [r][nloc]
    const int kc0 = blockIdx.x * 64;
    const int n0  = blockIdx.y * 64;
    const int t = threadIdx.x;

    {   // la rows kc0..kc0+63 (16 floats each) -> transposed
        int k = t >> 2, p = t & 3;
        float4 v = *(const float4*)(la + (size_t)(kc0 + k) * RLORA + p * 4);
        la_t[p * 4 + 0][k] = v.x; la_t[p * 4 + 1][k] = v.y;
        la_t[p * 4 + 2][k] = v.z; la_t[p * 4 + 3][k] = v.w;
    }
#pragma unroll
    for (int q = 0; q < 4; q++) {
        int idx = t + q * 256;
        int r = idx >> 6, nl = idx & 63;
        lb_s[r][nl] = lb[(size_t)r * Hd + n0 + nl];
    }
    __syncthreads();

    const int tn = t >> 4;            // 0..15 : n group of 4
    const int tk = t & 15;            // 0..15 : k group of 4 (warp-contiguous)
    const int nb = tn * 4, kb = tk * 4;

    float lv[4][4];
#pragma unroll
    for (int i = 0; i < 4; i++)
#pragma unroll
        for (int j = 0; j < 4; j++) lv[i][j] = 0.f;

#pragma unroll
    for (int r = 0; r < 16; r++) {
        float4 a = *(float4*)&la_t[r][kb];        // la[k][r] for 4 k
        float4 b = *(float4*)&lb_s[r][nb];        // lb[r][n] for 4 n
        lv[0][0] += b.x * a.x; lv[0][1] += b.x * a.y;
        lv[0][2] += b.x * a.z; lv[0][3] += b.x * a.w;
        lv[1][0] += b.y * a.x; lv[1][1] += b.y * a.y;
        lv[1][2] += b.y * a.z; lv[1][3] += b.y * a.w;
        lv[2][0] += b.z * a.x; lv[2][1] += b.z * a.y;
        lv[2][2] += b.z * a.z; lv[2][3] += b.z * a.w;
        lv[3][0] += b.w * a.x; lv[3][1] += b.w * a.y;
        lv[3][2] += b.w * a.z; lv[3][3] += b.w * a.w;
    }

#pragma unroll
    for (int nn = 0; nn < 4; nn++) {
        const int row = n0 + nb + nn;
        const size_t base = (size_t)row * Hd + kc0 + kb;
        const float am = absmax[base >> 6];
        int4 c = *(const int4*)(codes + base);
        float4 o;
        o.x = tf32r(c_nf4[c.x & 15] * am + lv[nn][0]);
        o.y = tf32r(c_nf4[c.y & 15] * am + lv[nn][1]);
        o.z = tf32r(c_nf4[c.z & 15] * am + lv[nn][2]);
        o.w = tf32r(c_nf4[c.w & 15] * am + lv[nn][3]);
        *(float4*)(W + base) = o;
    }
}

// ---------------------------------------------------------------------------
// Round x (fp32 -> tf32) into A (flat copy)
// ---------------------------------------------------------------------------
__global__ void roundx_kernel(const float* __restrict__ x, float* __restrict__ Aa)
{
    size_t base = ((size_t)blockIdx.x * blockDim.x + threadIdx.x) * 4;
    if (base >= (size_t)NELEM) return;
    float4 v = *(const float4*)(x + base);
    *(float4*)(Aa + base) =
        make_float4(tf32r(v.x), tf32r(v.y), tf32r(v.z), tf32r(v.w));
}

// ---------------------------------------------------------------------------
// V transpose: Vt[d_global][k] = V[k][d_global]   (4096 x 1024)
// ---------------------------------------------------------------------------
__global__ void vt_kernel(const float* __restrict__ V, float* __restrict__ Vt)
{
    __shared__ float tile[32][33];
    int x0 = blockIdx.x * 32;
    int y0 = blockIdx.y * 32;
    for (int i = threadIdx.y; i < 32; i += 8)
        tile[i][threadIdx.x] = V[(size_t)(y0 + i) * Hd + x0 + threadIdx.x];
    __syncthreads();
    for (int i = threadIdx.y; i < 32; i += 8)
        Vt[(size_t)(x0 + i) * Sq + y0 + threadIdx.x] = tile[threadIdx.x][i];
}

// ---------------------------------------------------------------------------
// cg2 projection GEMM (R7 proven version, unchanged)
// ---------------------------------------------------------------------------
#if TC_OK
template<bool ROUND>
__global__ __launch_bounds__(256, 1) __cluster_dims__(2, 1, 1)
void proj_gemm_cg2(const float* __restrict__ A, const float* __restrict__ B,
                   const float* __restrict__ bias, float* __restrict__ C, int CK)
{
    extern __shared__ char smem[];
    const unsigned sbase = smem_u32(smem);
    constexpr int ASUB = 128 * 128;
    constexpr int BSUB = 128 * 128;
    constexpr int ABUF = 2 * ASUB;
    constexpr int BBUF = 2 * BSUB;
    constexpr unsigned ABUF0 = 1024;
    constexpr unsigned BBUF0 = 1024 + 2 * ABUF;
    constexpr uint32_t IDESC =
        (1u << 4) | (2u << 7) | (2u << 10) | ((256 / 8) << 17) | (16u << 24);

    const int tid = threadIdx.x, wid = tid >> 5, lane = tid & 31;
    const int rank = blockIdx.x & 1;
    const int pair = blockIdx.x >> 1;
    const int bm = pair * 256 + rank * 128;
    const int bn = blockIdx.y * 256;

    if (wid == 0) TCGEN05_ALLOC_CG2(sbase, 256);
    if (tid == 0) {
        MBARRIER_INIT(sbase + 16, 2);
        MBARRIER_INIT(sbase + 24, 2);
        MBARRIER_INIT(sbase + 32, 1);
        MBARRIER_INIT(sbase + 40, 1);
    }
    __syncthreads();
    unsigned tmem;
    asm volatile("ld.shared.b32 %0, [%1];" : "=r"(tmem) : "r"(sbase));
    if (wid == 0) TCGEN05_RELINQUISH_CG2();
    CLUSTER_SYNC();

    bool isel = false;
    if (wid == 0) isel = elect_one();

    auto load_chunk = [&](int c) {
        int b = c & 1;
        unsigned sA = sbase + ABUF0 + b * ABUF;
        unsigned sB = sbase + BBUF0 + b * BBUF;
        const float* Ab = A + (size_t)bm * Hd + c * 64;
#pragma unroll
        for (int l = 0; l < 8; l++) {
            int s = tid + l * 256;
            int sub = s >> 10, w = s & 1023;
            int r = w >> 3, i = w & 7;
            cpa16(sA + sub * ASUB + swz(r * 128 + i * 16),
                  Ab + (size_t)r * Hd + sub * 32 + i * 4);
        }
        const float* Bb = B + (size_t)(bn + rank * 128) * Hd + c * 64;
#pragma unroll
        for (int l = 0; l < 8; l++) {
            int s = tid + l * 256;
            int sub = s >> 10, w = s & 1023;
            int r = w >> 3, i = w & 7;
            cpa16(sB + sub * BSUB + swz(r * 128 + i * 16),
                  Bb + (size_t)r * Hd + sub * 32 + i * 4);
        }
        asm volatile("cp.async.commit_group;" ::: "memory");
    };

    load_chunk(0);
    load_chunk(1);

    for (int c = 0; c < CK; ++c) {
        int b = c & 1;
        if (c + 1 < CK) asm volatile("cp.async.wait_group 1;" ::: "memory");
        else            asm volatile("cp.async.wait_group 0;" ::: "memory");
        __syncthreads();
        if (tid == 0) {
            FENCE_PROXY_ASYNC();
            MBARRIER_ARRIVE_RANK0(sbase + 16 + 8 * b);
        }
        if (rank == 0 && isel) {
            MBARRIER_WAIT_PARITY_CL(sbase + 16 + 8 * b, (c >> 1) & 1);
#pragma unroll
            for (int j = 0; j < 2; j++) {
                uint64_t ad = MAKE_SMEM_DESC(sbase + ABUF0 + b * ABUF + j * ASUB);
                uint64_t bd = MAKE_SMEM_DESC(sbase + BBUF0 + b * BBUF + j * BSUB);
#pragma unroll
                for (int s = 0; s < 4; s++)
                    mma_tf32_cg2(tmem, ad + s * 2, bd + s * 2, IDESC,
                                 (c > 0 || j > 0 || s > 0) ? 1u : 0u);
            }
            TCGEN05_COMMIT_MC_CG2(sbase + 32 + 8 * b, 0x3);
        }
        if (c + 2 < CK) {
            MBARRIER_WAIT_PARITY(sbase + 32 + 8 * b, (c >> 1) & 1);
            load_chunk(c + 2);
        }
    }
    {
        int c = CK - 1, b = c & 1;
        MBARRIER_WAIT_PARITY(sbase + 32 + 8 * b, (c >> 1) & 1);
    }
    TCGEN05_FENCE_AFTER();

    if (wid < 4) {
        int row = bm + wid * 32 + lane;
#pragma unroll
        for (int nb = 0; nb < 8; nb++) {
            uint32_t r[32];
            TCGEN05_LD_32X32B_X32(r, tmem + nb * 32);
            TCGEN05_WAIT_LD();
            int col0 = bn + nb * 32;
            float v[32];
#pragma unroll
            for (int j = 0; j < 32; j++) {
                float d = __uint_as_float(r[j]) + bias[col0 + j];
                if (ROUND) d = tf32r(d);
                v[j] = d;
            }
            float4* dst = (float4*)(C + (size_t)row * Hd + col0);
#pragma unroll
            for (int q = 0; q < 8; q++)
                dst[q] = make_float4(v[4*q], v[4*q+1], v[4*q+2], v[4*q+3]);
        }
    }
    __syncthreads();
    CLUSTER_SYNC();
    if (wid == 0) TCGEN05_DEALLOC_CG2(tmem, 256);
    CLUSTER_SYNC();
}
#else
// generic fallback: plain FFMA tile 128x256 per CTA
template<bool ROUND>
__global__ __launch_bounds__(256, 1) __cluster_dims__(2, 1, 1)
void proj_gemm_cg2(const float* __restrict__ A, const float* __restrict__ B,
                   const float* __restrict__ bias, float* __restrict__ C, int CK)
{
    extern __shared__ char smem[];
    float* As = (float*)smem;
    float* Bs = (float*)(smem + 16 * 128 * 4);
    const int tid = threadIdx.x;
    const int rank = blockIdx.x & 1;
    const int bm = (blockIdx.x >> 1) * 256 + rank * 128;
    const int bn = blockIdx.y * 256;
    const int Kd = CK * 64;
    const int tx = tid & 15, ty = tid >> 4;
    float acc[8][16];
#pragma unroll
    for (int i = 0; i < 8; i++)
#pragma unroll
        for (int j = 0; j < 16; j++) acc[i][j] = 0.f;

    for (int k0 = 0; k0 < Kd; k0 += 16) {
#pragma unroll
        for (int l = 0; l < 2; l++) {
            int f = tid + l * 256;
            int r = f >> 2, c4 = f & 3;
            float4 v = *(const float4*)(A + (size_t)(bm + r) * Hd + k0 + c4 * 4);
            As[(c4 * 4 + 0) * 128 + r] = v.x; As[(c4 * 4 + 1) * 128 + r] = v.y;
            As[(c4 * 4 + 2) * 128 + r] = v.z; As[(c4 * 4 + 3) * 128 + r] = v.w;
        }
#pragma unroll
        for (int l = 0; l < 4; l++) {
            int f = tid + l * 256;
            int r = f >> 2, c4 = f & 3;
            float4 v = *(const float4*)(B + (size_t)(bn + r) * Hd + k0 + c4 * 4);
            Bs[(c4 * 4 + 0) * 256 + r] = v.x; Bs[(c4 * 4 + 1) * 256 + r] = v.y;
            Bs[(c4 * 4 + 2) * 256 + r] = v.z; Bs[(c4 * 4 + 3) * 256 + r] = v.w;
        }
        __syncthreads();
#pragma unroll
        for (int kk = 0; kk < 16; kk++) {
            float ar[8], br[16];
#pragma unroll
            for (int i = 0; i < 8; i++) ar[i] = As[kk * 128 + ty * 8 + i];
#pragma unroll
            for (int j = 0; j < 16; j++) br[j] = Bs[kk * 256 + tx * 16 + j];
#pragma unroll
            for (int i = 0; i < 8; i++)
#pragma unroll
                for (int j = 0; j < 16; j++)
                    acc[i][j] += ar[i] * br[j];
        }
        __syncthreads();
    }
#pragma unroll
    for (int i = 0; i < 8; i++) {
        int row = bm + ty * 8 + i;
#pragma unroll
        for (int j = 0; j < 16; j++) {
            int col = bn + tx * 16 + j;
            float d = acc[i][j] + bias[col];
            if (ROUND) d = tf32r(d);
            C[(size_t)row * Hd + col] = d;
        }
    }
}
#endif

// ---------------------------------------------------------------------------
// cg1 GEMM for attention (scores / PV) — R7 proven version, unchanged.
// MODE 1: C = D*scale + mask[row,col]   MODE 2: C = D
// ---------------------------------------------------------------------------
template<int NT, int MODE, bool ROUND>
__global__ __launch_bounds__(256, 1)
void tf32_gemm(const float* __restrict__ A, long lda, long zA,
               const float* __restrict__ B, long ldb, long zB,
               float* __restrict__ C, long ldc, long zC,
               const float* __restrict__ aux, int CK)
{
#if TC_OK
    extern __shared__ char smem[];
    const unsigned sbase = smem_u32(smem);
    constexpr int ASUB = 128 * 128;
    constexpr int BSUB = NT * 128;
    constexpr int ABUF = 2 * ASUB;
    constexpr int BBUF = 2 * BSUB;
    constexpr unsigned ABUF0 = 1024;
    constexpr unsigned BBUF0 = 1024 + 2 * ABUF;
    constexpr uint32_t IDESC =
        (1u << 4) | (2u << 7) | (2u << 10) | ((NT / 8) << 17) | (8u << 24);

    const int tid = threadIdx.x, wid = tid >> 5, lane = tid & 31;
    const int bm = blockIdx.y * 128, bn = blockIdx.x * NT, bz = blockIdx.z;
    const float* Az = A + (size_t)zA * bz;
    const float* Bz = B + (size_t)zB * bz;
    float*       Cz = C + (size_t)zC * bz;

    if (wid == 0) TCGEN05_ALLOC(sbase, 256);
    if (tid == 0) { MBARRIER_INIT(sbase + 16, 1); MBARRIER_INIT(sbase + 24, 1); }
    __syncthreads();
    unsigned tmem;
    asm volatile("ld.shared.b32 %0, [%1];" : "=r"(tmem) : "r"(sbase));
    if (wid == 0) TCGEN05_RELINQUISH();

    bool isel = false;
    if (wid == 0) isel = elect_one();

    auto load_chunk = [&](int c) {
        int b = c & 1;
        unsigned sA = sbase + ABUF0 + b * ABUF;
        unsigned sB = sbase + BBUF0 + b * BBUF;
        const float* Ab = Az + (size_t)bm * lda + c * 64;
#pragma unroll
        for (int l = 0; l < 8; l++) {
            int s = tid + l * 256;
            int sub = s >> 10, w = s & 1023;
            int r = w >> 3, i = w & 7;
            cpa16(sA + sub * ASUB + swz(r * 128 + i * 16),
                  Ab + (size_t)r * lda + sub * 32 + i * 4);
        }
        const float* Bb = Bz + (size_t)bn * ldb + c * 64;
#pragma unroll
        for (int l = 0; l < NT / 16; l++) {
            int s = tid + l * 256;
            int sub = s / (NT * 8), w = s % (NT * 8);
            int r = w >> 3, i = w & 7;
            cpa16(sB + sub * BSUB + swz(r * 128 + i * 16),
                  Bb + (size_t)r * ldb + sub * 32 + i * 4);
        }
        asm volatile("cp.async.commit_group;" ::: "memory");
    };

    load_chunk(0);
    load_chunk(1);

    for (int c = 0; c < CK; ++c) {
        int b = c & 1;
        if (c + 1 < CK) asm volatile("cp.async.wait_group 1;" ::: "memory");
        else            asm volatile("cp.async.wait_group 0;" ::: "memory");
        __syncthreads();
        if (isel) {
            FENCE_PROXY_ASYNC();
#pragma unroll
            for (int j = 0; j < 2; j++) {
                uint64_t ad = MAKE_SMEM_DESC(sbase + ABUF0 + b * ABUF + j * ASUB);
                uint64_t bd = MAKE_SMEM_DESC(sbase + BBUF0 + b * BBUF + j * BSUB);
#pragma unroll
                for (int s = 0; s < 4; s++)
                    mma_tf32(tmem, ad + s * 2, bd + s * 2, IDESC,
                             (c > 0 || j > 0 || s > 0) ? 1u : 0u);
            }
            TCGEN05_COMMIT(sbase + 16 + 8 * b);
        }
        if (c + 2 < CK) {
            MBARRIER_WAIT_PARITY(sbase + 16 + 8 * b, (c >> 1) & 1);
            load_chunk(c + 2);
        }
    }
    {
        int c = CK - 1, b = c & 1;
        MBARRIER_WAIT_PARITY(sbase + 16 + 8 * b, (c >> 1) & 1);
    }
    TCGEN05_FENCE_AFTER();

    if (wid < 4) {
        int row = bm + wid * 32 + lane;
#pragma unroll
        for (int nb = 0; nb < NT / 32; nb++) {
            uint32_t r[32];
            TCGEN05_LD_32X32B_X32(r, tmem + nb * 32);
            TCGEN05_WAIT_LD();
            int col0 = bn + nb * 32;
            float v[32];
#pragma unroll
            for (int j = 0; j < 32; j++) {
                float d = __uint_as_float(r[j]);
                if (MODE == 1) d = d * 0.08838834764831845f
                                   + aux[(size_t)row * Sq + col0 + j];
                if (ROUND) d = tf32r(d);
                v[j] = d;
            }
            float4* dst = (float4*)(Cz + (size_t)row * ldc + col0);
#pragma unroll
            for (int q = 0; q < 8; q++)
                dst[q] = make_float4(v[4*q], v[4*q+1], v[4*q+2], v[4*q+3]);
        }
    }
    __syncthreads();
    if (wid == 0) TCGEN05_DEALLOC(tmem, 256);

#else  // ------- generic-arch FFMA fallback -------------
    extern __shared__ char smem[];
    float* As = (float*)smem;
    float* Bs = (float*)(smem + 16 * 128 * 4);
    const int tid = threadIdx.x;
    const int bm = blockIdx.y * 128, bn = blockIdx.x * NT, bz = blockIdx.z;
    const float* Az = A + (size_t)zA * bz;
    const float* Bz = B + (size_t)zB * bz;
    float*       Cz = C + (size_t)zC * bz;
    const int Kd = CK * 64;
    const int tx = tid & 15, ty = tid >> 4;
    constexpr int JW = NT / 16;
    float acc[8][JW];
#pragma unroll
    for (int i = 0; i < 8; i++)
#pragma unroll
        for (int j = 0; j < JW; j++) acc[i][j] = 0.f;

    for (int k0 = 0; k0 < Kd; k0 += 16) {
#pragma unroll
        for (int l = 0; l < 2; l++) {
            int f = tid + l * 256;
            int r = f >> 2, c4 = f & 3;
            float4 v = *(const float4*)(Az + (size_t)(bm + r) * lda + k0 + c4 * 4);
            As[(c4 * 4 + 0) * 128 + r] = v.x; As[(c4 * 4 + 1) * 128 + r] = v.y;
            As[(c4 * 4 + 2) * 128 + r] = v.z; As[(c4 * 4 + 3) * 128 + r] = v.w;
        }
#pragma unroll
        for (int l = 0; l < NT / 64; l++) {
            int f = tid + l * 256;
            int r = f >> 2, c4 = f & 3;
            float4 v = *(const float4*)(Bz + (size_t)(bn + r) * ldb + k0 + c4 * 4);
            Bs[(c4 * 4 + 0) * NT + r] = v.x; Bs[(c4 * 4 + 1) * NT + r] = v.y;
            Bs[(c4 * 4 + 2) * NT + r] = v.z; Bs[(c4 * 4 + 3) * NT + r] = v.w;
        }
        __syncthreads();
#pragma unroll
        for (int kk = 0; kk < 16; kk++) {
            float ar[8], br[JW];
#pragma unroll
            for (int i = 0; i < 8; i++) ar[i] = As[kk * 128 + ty * 8 + i];
#pragma unroll
            for (int j = 0; j < JW; j++) br[j] = Bs[kk * NT + tx * JW + j];
#pragma unroll
            for (int i = 0; i < 8; i++)
#pragma unroll
                for (int j = 0; j < JW; j++)
                    acc[i][j] += ar[i] * br[j];
        }
        __syncthreads();
    }
#pragma unroll
    for (int i = 0; i < 8; i++) {
        int row = bm + ty * 8 + i;
#pragma unroll
        for (int j = 0; j < JW; j++) {
            int col = bn + tx * JW + j;
            float d = acc[i][j];
            if (MODE == 1) d = d * 0.08838834764831845f
                               + aux[(size_t)row * Sq + col];
            if (ROUND) d = tf32r(d);
            Cz[(size_t)row * ldc + col] = d;
        }
    }
#endif
}

// ---------------------------------------------------------------------------
// Single-pass row softmax (unchanged)
// ---------------------------------------------------------------------------
__global__ void softmax_kernel(float* __restrict__ S)
{
    size_t row = blockIdx.x;
    float4* p = (float4*)(S + row * Sq);
    int tid = threadIdx.x;
    float4 v = p[tid];
    __shared__ float red[8];

    float m = fmaxf(fmaxf(v.x, v.y), fmaxf(v.z, v.w));
#pragma unroll
    for (int o = 16; o > 0; o >>= 1) m = fmaxf(m, __shfl_xor_sync(~0u, m, o));
    if ((tid & 31) == 0) red[tid >> 5] = m;
    __syncthreads();
    m = red[0];
#pragma unroll
    for (int w = 1; w < 8; w++) m = fmaxf(m, red[w]);
    __syncthreads();

    float4 e;
    e.x = expf(v.x - m); e.y = expf(v.y - m);
    e.z = expf(v.z - m); e.w = expf(v.w - m);
    float s = (e.x + e.y) + (e.z + e.w);
#pragma unroll
    for (int o = 16; o > 0; o >>= 1) s += __shfl_xor_sync(~0u, s, o);
    if ((tid & 31) == 0) red[tid >> 5] = s;
    __syncthreads();
    s = red[0];
#pragma unroll
    for (int w = 1; w < 8; w++) s += red[w];
    float inv = 1.0f / s;
    p[tid] = make_float4(tf32r(e.x * inv), tf32r(e.y * inv),
                         tf32r(e.z * inv), tf32r(e.w * inv));
}

// ---------------------------------------------------------------------------
// Exact rank-k selection — BATCHED across all 6 tensors (R11 proven version).
// ---------------------------------------------------------------------------
__device__ __forceinline__ void block_pick(const unsigned* __restrict__ h,
                                           unsigned long long k,
                                           unsigned* sps, unsigned long long* spr,
                                           unsigned& bin, unsigned long long& krem)
{
    int t = threadIdx.x;
    unsigned v[8]; unsigned s = 0;
#pragma unroll
    for (int i = 0; i < 8; i++) { v[i] = h[t * 8 + i]; s += v[i]; }
    sps[t] = s;
    __syncthreads();
    if (t == 0) {
        unsigned long long cum = 0; int ct = 0;
        while (ct < 255 && cum + sps[ct] < k) { cum += sps[ct]; ct++; }
        spr[0] = (unsigned long long)ct; spr[1] = k - cum;
    }
    __syncthreads();
    if (t == (int)spr[0]) {
        unsigned long long kk = spr[1]; int b = 7;
#pragma unroll
        for (int i = 0; i < 8; i++) {
            if (kk <= v[i]) { b = i; break; }
            kk -= v[i];
        }
        spr[0] = (unsigned long long)(t * 8 + b); spr[1] = kk;
    }
    __syncthreads();
    bin = (unsigned)spr[0]; krem = spr[1];
    __syncthreads();
}

__global__ void sel_clear0()
{
    int t = blockIdx.x * blockDim.x + threadIdx.x;   // grid 48x256 = 12288
    if (t < 6 * 2048) { ((unsigned*)g_h1)[t] = 0; ((unsigned*)g_h2)[t] = 0; }
    if (t < 6 * 1024) ((unsigned*)g_h3)[t] = 0;
}

__global__ void sel_h1_all(SelArgs a)
{
    int z = blockIdx.z;
    const float* data = a.d[z];
    size_t n4 = (size_t)a.n[z] >> 2;
    __shared__ unsigned sh[2048];
    for (int i = threadIdx.x; i < 2048; i += 256) sh[i] = 0;
    __syncthreads();
    size_t stride = (size_t)gridDim.x * 256;
    unsigned zc = 0;
    for (size_t f = (size_t)blockIdx.x * 256 + threadIdx.x; f < n4; f += stride) {
        float4 d = *(const float4*)(data + (f << 2));
        unsigned uu[4] = { __float_as_uint(d.x), __float_as_uint(d.y),
                           __float_as_uint(d.z), __float_as_uint(d.w) };
#pragma unroll
        for (int j = 0; j < 4; j++) {
            unsigned u = uu[j] & 0x7FFFFFFFu;
            if (u == 0u) zc++;
            else atomicAdd(&sh[u >> 21], 1u);
        }
    }
    if (zc) atomicAdd(&sh[0], zc);
    __syncthreads();
    for (int i = threadIdx.x; i < 2048; i += 256)
        if (sh[i]) atomicAdd(&g_h1[z][i], sh[i]);
}

__global__ void sel_h2_all(SelArgs a)
{
    int z = blockIdx.z;
    const float* data = a.d[z];
    size_t n4 = (size_t)a.n[z] >> 2;
    __shared__ unsigned sh[2048];
    __shared__ unsigned sps[256]; __shared__ unsigned long long spr[2];
    unsigned b1; unsigned long long kr;
    block_pick(g_h1[z], a.k[z], sps, spr, b1, kr);
    for (int i = threadIdx.x; i < 2048; i += 256) sh[i] = 0;
    __syncthreads();
    unsigned pref = b1 << 21;
    size_t stride = (size_t)gridDim.x * 256;
    for (size_t f = (size_t)blockIdx.x * 256 + threadIdx.x; f < n4; f += stride) {
        float4 d = *(const float4*)(data + (f << 2));
        unsigned uu[4] = { __float_as_uint(d.x), __float_as_uint(d.y),
                           __float_as_uint(d.z), __float_as_uint(d.w) };
#pragma unroll
        for (int j = 0; j < 4; j++) {
            unsigned u = uu[j] & 0x7FFFFFFFu;
            if ((u & 0xFFE00000u) == pref)
                atomicAdd(&sh[(u >> 10) & 0x7FFu], 1u);
        }
    }
    __syncthreads();
    for (int i = threadIdx.x; i < 2048; i += 256)
        if (sh[i]) atomicAdd(&g_h2[z][i], sh[i]);
}

__global__ void sel_h3_all(SelArgs a)
{
    int z = blockIdx.z;
    const float* data = a.d[z];
    size_t n4 = (size_t)a.n[z] >> 2;
    __shared__ unsigned sh[1024];
    __shared__ unsigned sps[256]; __shared__ unsigned long long spr[2];
    unsigned b1, b2; unsigned long long k2, kr;
    block_pick(g_h1[z], a.k[z], sps, spr, b1, k2);
    block_pick(g_h2[z], k2,     sps, spr, b2, kr);
    for (int i = threadIdx.x; i < 1024; i += 256) sh[i] = 0;
    __syncthreads();
    unsigned pref = (b1 << 21) | (b2 << 10);
    size_t stride = (size_t)gridDim.x * 256;
    for (size_t f = (size_t)blockIdx.x * 256 + threadIdx.x; f < n4; f += stride) {
        float4 d = *(const float4*)(data + (f << 2));
        unsigned uu[4] = { __float_as_uint(d.x), __float_as_uint(d.y),
                           __float_as_uint(d.z), __float_as_uint(d.w) };
#pragma unroll
        for (int j = 0; j < 4; j++) {
            unsigned u = uu[j] & 0x7FFFFFFFu;
            if ((u & 0xFFFFFC00u) == pref)
                atomicAdd(&sh[u & 0x3FFu], 1u);
        }
    }
    __syncthreads();
    for (int i = threadIdx.x; i < 1024; i += 256)
        if (sh[i]) atomicAdd(&g_h3[z][i], sh[i]);
}

__global__ void sel_fin_all(SelArgs a, float* __restrict__ out)
{
    int z = blockIdx.x;                        // 6 blocks
    __shared__ unsigned sps[256]; __shared__ unsigned long long spr[2];
    unsigned b1, b2, b3; unsigned long long k2, k3;
    block_pick(g_h1[z], a.k[z], sps, spr, b1, k2);
    block_pick(g_h2[z], k2,     sps, spr, b2, k3);
    {
        int t = threadIdx.x;
        unsigned v[4]; unsigned s = 0;
#pragma unroll
        for (int i = 0; i < 4; i++) { v[i] = g_h3[z][t * 4 + i]; s += v[i]; }
        sps[t] = s;
        __syncthreads();
        if (t == 0) {
            unsigned long long cum = 0; int ct = 0;
            while (ct < 255 && cum + sps[ct] < k3) { cum += sps[ct]; ct++; }
            spr[0] = (unsigned long long)ct; spr[1] = k3 - cum;
        }
        __syncthreads();
        if (t == (int)spr[0]) {
            unsigned long long kk = spr[1]; int b = 3;
#pragma unroll
            for (int i = 0; i < 4; i++) {
                if (kk <= v[i]) { b = i; break; }
                kk -= v[i];
            }
            spr[0] = (unsigned long long)(t * 4 + b);
        }
        __syncthreads();
        b3 = (unsigned)spr[0];
        __syncthreads();
    }
    // re-zero this tensor's hists (graph-replay safety)
    for (int i = threadIdx.x; i < 2048; i += 256) { g_h1[z][i] = 0; g_h2[z][i] = 0; }
    for (int i = threadIdx.x; i < 1024; i += 256) g_h3[z][i] = 0;
    if (threadIdx.x == 0)
        out[z] = __uint_as_float((b1 << 21) | (b2 << 10) | b3);
}

// ---------------------------------------------------------------------------
// Host orchestration
// ---------------------------------------------------------------------------
extern "C" void kernel_launch(void* const* d_in, const int* in_sizes, int n_in,
                              void* d_out, int out_size)
{
    const float* x    = (const float*)d_in[0];
    const int*   codes[4];
    const float *amax[4], *bias[4], *la[4], *lb[4];
    for (int p = 0; p < 4; p++) {
        codes[p] = (const int*)  d_in[1 + p * 5 + 0];
        amax[p]  = (const float*)d_in[1 + p * 5 + 1];
        bias[p]  = (const float*)d_in[1 + p * 5 + 2];
        la[p]    = (const float*)d_in[1 + p * 5 + 3];
        lb[p]    = (const float*)d_in[1 + p * 5 + 4];
    }
    const float* mask = (const float*)d_in[21];
    float* out = (float*)d_out;

    float *pAa, *pBa, *pQ, *pK, *pV, *pVt, *pAttn;
    cudaGetSymbolAddress((void**)&pAa,   g_Aaug);
    cudaGetSymbolAddress((void**)&pBa,   g_Baug);
    cudaGetSymbolAddress((void**)&pQ,    g_q);
    cudaGetSymbolAddress((void**)&pK,    g_k);
    cudaGetSymbolAddress((void**)&pV,    g_v);
    cudaGetSymbolAddress((void**)&pVt,   g_vt);
    cudaGetSymbolAddress((void**)&pAttn, g_attn);

    const int SMCG2 = 1024 + 4 * (2 * 128 * 128);                        // 132096
    const int SM256 = 1024 + 2 * (2 * 128 * 128) + 2 * (2 * 256 * 128);  // 197632
    const int SM128 = 1024 + 2 * (2 * 128 * 128) + 2 * (2 * 128 * 128);  // 132096
    cudaFuncSetAttribute(proj_gemm_cg2<true>,
        cudaFuncAttributeMaxDynamicSharedMemorySize, SMCG2);
    cudaFuncSetAttribute(proj_gemm_cg2<false>,
        cudaFuncAttributeMaxDynamicSharedMemorySize, SMCG2);
    cudaFuncSetAttribute(tf32_gemm<256, 1, false>,
        cudaFuncAttributeMaxDynamicSharedMemorySize, SM256);
    cudaFuncSetAttribute(tf32_gemm<128, 2, true>,
        cudaFuncAttributeMaxDynamicSharedMemorySize, SM128);

    const int CKP = Hd / 64;        // 64 chunks for projections

    sel_clear0<<<48, 256>>>();
    roundx_kernel<<<NELEM / 4 / 256, 256>>>(x, pAa);

    // --- Q, K, V projections (cg2 pair tiles, lora folded in weights) ---
    float* qkv[3] = { pQ, pK, pV };
    for (int p = 0; p < 3; p++) {
        dequant_kernel<<<dim3(64, 64), 256>>>(codes[p], amax[p], la[p], lb[p], pBa);
        proj_gemm_cg2<true><<<dim3(8, 16, 1), 256, SMCG2>>>(
            pAa, pBa, bias[p], qkv[p], CKP);
    }

    // --- Attention ---
    tf32_gemm<256, 1, false><<<dim3(4, 8, NHEAD), 256, SM256>>>(
        pQ, Hd, HDIM, pK, Hd, HDIM, pAttn, Sq, (long)Sq * Sq, mask, HDIM / 64);
    softmax_kernel<<<NHEAD * Sq, 256>>>(pAttn);
    vt_kernel<<<dim3(Hd / 32, Sq / 32), dim3(32, 8)>>>(pV, pVt);
    tf32_gemm<128, 2, true><<<dim3(1, 8, NHEAD), 256, SM128>>>(
        pAttn, Sq, (long)Sq * Sq, pVt, Sq, (long)HDIM * Sq,
        pAa, Hd, HDIM, nullptr, Sq / 64);

    // --- Output projection -> d_out ---
    dequant_kernel<<<dim3(64, 64), 256>>>(codes[3], amax[3], la[3], lb[3], pBa);
    proj_gemm_cg2<false><<<dim3(8, 16, 1), 256, SMCG2>>>(
        pAa, pBa, bias[3], out, CKP);

    // --- kth values: [x, qh, kh, vh, a, o] (batched, grid.z = tensor) ---
    SelArgs sa;
    sa.d[0] = x;     sa.n[0] = NELEM; sa.k[0] = NELEM / 2;
    sa.d[1] = pQ;    sa.n[1] = NELEM; sa.k[1] = NELEM / 2;
    sa.d[2] = pK;    sa.n[2] = NELEM; sa.k[2] = NELEM / 2;
    sa.d[3] = pV;    sa.n[3] = NELEM; sa.k[3] = NELEM / 2;
    sa.d[4] = pAttn; sa.n[4] = AELEM; sa.k[4] = AELEM / 2;
    sa.d[5] = pAa;   sa.n[5] = NELEM; sa.k[5] = NELEM / 2;

    sel_h1_all <<<dim3(512, 1, 6), 256>>>(sa);
    sel_h2_all <<<dim3(512, 1, 6), 256>>>(sa);
    sel_h3_all <<<dim3(512, 1, 6), 256>>>(sa);
    sel_fin_all<<<6, 256>>>(sa, out + NELEM);
}